// round 15
// baseline (speedup 1.0000x reference)
#include <cuda_runtime.h>
#include <cuda_fp16.h>
#include <cstdint>
#include <math.h>

typedef __half hf;

#define Bb 4
#define Lq 1024
#define Dd 1024
#define Hh 8
#define Pp 1024
#define Ff 4096
#define DKc 128

#define SQKV ((long)Bb*Hh*Lq*DKc)

// ---------------- scratch ----------------
__device__ hf g_xn[Bb*Lq*Dd];
__device__ hf g_qkv[3*Bb*Hh*Lq*DKc];      // q | k | v, each [B,H,L,DK]
__device__ hf g_h [Bb*Lq*Ff];
__device__ hf g_attn[(size_t)Bb*Hh*Lq*Lq];
__device__ hf g_path[(size_t)Bb*Hh*Lq*Pp];
__device__ hf g_wc [Dd*3*Dd];             // [1024][3072] = wq|wk|wv columns, K-major
__device__ hf g_wo [Dd*Dd];               // K-major natural
__device__ hf g_w1 [Dd*Ff];               // K-major natural
__device__ hf g_w2 [Ff*Dd];               // K-major natural
__device__ hf g_rk [Bb*Hh*Pp*DKc];
__device__ hf g_rv [Bb*Hh*Pp*DKc];
__device__ hf g_scores[(size_t)Bb*Hh*Lq*Lq];   // fp16 final scores
__device__ hf g_qr[(size_t)Bb*Hh*Lq*Pp];       // fp16 qr
__device__ float g_x[Bb*Lq*Dd];

// ---------------- helpers ----------------
__device__ __forceinline__ void ldsm4(uint32_t r[4], const hf* p){
  uint32_t a = (uint32_t)__cvta_generic_to_shared(p);
  asm volatile("ldmatrix.sync.aligned.m8n8.x4.shared.b16 {%0,%1,%2,%3},[%4];"
    :"=r"(r[0]),"=r"(r[1]),"=r"(r[2]),"=r"(r[3]):"r"(a));
}
__device__ __forceinline__ void ldsm4t(uint32_t r[4], const hf* p){
  uint32_t a = (uint32_t)__cvta_generic_to_shared(p);
  asm volatile("ldmatrix.sync.aligned.m8n8.x4.trans.shared.b16 {%0,%1,%2,%3},[%4];"
    :"=r"(r[0]),"=r"(r[1]),"=r"(r[2]),"=r"(r[3]):"r"(a));
}
__device__ __forceinline__ void mma_f16(float c[4], const uint32_t a[4], const uint32_t b[2]){
  asm volatile("mma.sync.aligned.m16n8k16.row.col.f32.f16.f16.f32 "
    "{%0,%1,%2,%3},{%4,%5,%6,%7},{%8,%9},{%0,%1,%2,%3};"
    :"+f"(c[0]),"+f"(c[1]),"+f"(c[2]),"+f"(c[3])
    :"r"(a[0]),"r"(a[1]),"r"(a[2]),"r"(a[3]),"r"(b[0]),"r"(b[1]));
}
__device__ __forceinline__ void cpa16(hf* dst, const hf* src){
  uint32_t d = (uint32_t)__cvta_generic_to_shared(dst);
  asm volatile("cp.async.cg.shared.global [%0],[%1],16;"::"r"(d),"l"(src));
}
__device__ __forceinline__ void cpa_commit(){ asm volatile("cp.async.commit_group;"); }
template<int N> __device__ __forceinline__ void cpa_wait(){ asm volatile("cp.async.wait_group %0;"::"n"(N)); }

__device__ __forceinline__ float gelu_f(float u){
  return 0.5f*u*(1.f + tanhf(0.7978845608028654f*(u + 0.044715f*u*u*u)));
}
__device__ __forceinline__ uint32_t packh2(float a, float b){
  __half2 h; h.x = __float2half_rn(a); h.y = __float2half_rn(b);
  return *(uint32_t*)&h;
}

// ---------------- fp16 tensor-core GEMM, 64x128 tile, 3-stage pipeline ----------------
// A[M][K] row-major. BTRANS=0: B[N][K] row-major. BTRANS=1: B[K][N] row-major (ldb=N).
// 8 warps: warp grid 2x4, each warp 32x32. M_MERGE: 2nd K-segment accumulated.
#define M_HOUT  0
#define M_QKV   2
#define M_GELU  3
#define M_RES   4
#define M_SCORE 5
#define M_MERGE 6

#define PITCH 40
#define APLANE (64*PITCH)     // 2560 halves
#define BPL    (128*PITCH)    // 5120 halves (covers both B layouts)
#define BP     136            // pitch for K-major B rows

template<int MODE, int BTRANS>
__global__ __launch_bounds__(256, 3)
void hgemm(const hf* __restrict__ A, const hf* __restrict__ Bm,
           const hf* __restrict__ A2, const hf* __restrict__ B2,
           const float* __restrict__ bias, const float* __restrict__ bias2,
           const float* __restrict__ bias3,
           const float* __restrict__ res,
           const int* __restrict__ pm, const int* __restrict__ msk,
           const hf* __restrict__ qrh,
           float* __restrict__ Cf, hf* __restrict__ Ch,
           int N, int K, int K2,
           long sA, long sB, long sA2, long sB2, long sC)
{
  __shared__ hf As[3][APLANE];
  __shared__ hf Bs[3][BPL];
  long z = blockIdx.z;
  long cbase = z*sC;
  int tid = threadIdx.x, warp = tid>>5, lane = tid&31;
  int bm = blockIdx.y*64, bn = blockIdx.x*128;
  int wm = (warp>>2)*32, wn = (warp&3)*32;
  float c[2][4][4] = {};
  int frag_r = ((lane>>3)&1)*8 + (lane&7);
  int frag_k = (lane>>4)*8;

  // A staging: 64 rows x 2 segs, threads 0..127
  int r2 = tid>>1, s2 = (tid&1)*16;
  const hf* pa1 = A  + z*sA + (long)(bm+r2)*K + s2;
  const hf* pa2 = (MODE==M_MERGE) ? (A2 + z*sA2 + (long)(bm+r2)*K2 + s2) : pa1;
  // B N-major: 128 rows x 2 segs (all threads)
  const hf* pb1n = Bm + z*sB + (long)(bn+r2)*K + s2;
  // B K-major: 32 rows x 8 segs (all threads)
  int br = tid>>3, bc8 = (tid&7)*16;
  const hf* pb1t = Bm + z*sB + (long)br*N + bn + bc8;
  const hf* pb2t = (MODE==M_MERGE) ? (B2 + z*sB2 + (long)br*N + bn + bc8) : pb1t;

  const int T1 = K >> 5;
  const int T  = T1 + (K2 >> 5);

  auto ld = [&](int cchunk){
    int st = cchunk % 3;
    bool seg1 = (cchunk < T1);
    int off = seg1 ? (cchunk<<5) : ((cchunk-T1)<<5);
    if(tid < 128){
      const hf* pa = seg1 ? pa1 : pa2;
      cpa16(&As[st][r2*PITCH + s2],     pa + off);
      cpa16(&As[st][r2*PITCH + s2 + 8], pa + off + 8);
    }
    if(BTRANS){
      const hf* pb = seg1 ? pb1t : pb2t;
      cpa16(&Bs[st][br*BP + bc8],       pb + (long)off*N);
      cpa16(&Bs[st][br*BP + bc8 + 8],   pb + (long)off*N + 8);
    } else {
      cpa16(&Bs[st][r2*PITCH + s2],     pb1n + off);
      cpa16(&Bs[st][r2*PITCH + s2 + 8], pb1n + off + 8);
    }
  };

  ld(0); cpa_commit();
  if(T>1){ ld(1); cpa_commit(); }
  for(int t=0;t<T;t++){
    if(t+1<T) cpa_wait<1>(); else cpa_wait<0>();
    __syncthreads();
    int st = t % 3;
#pragma unroll
    for(int kk=0;kk<32;kk+=16){
      uint32_t a4[2][4], b2[4][2];
#pragma unroll
      for(int mi=0;mi<2;mi++)
        ldsm4(a4[mi], &As[st][(wm+mi*16+frag_r)*PITCH + kk + frag_k]);
#pragma unroll
      for(int p=0;p<2;p++){
        uint32_t t4[4];
        if(BTRANS){
          ldsm4t(t4, &Bs[st][(kk+frag_r)*BP + wn + p*16 + frag_k]);
          b2[2*p][0]=t4[0]; b2[2*p][1]=t4[1]; b2[2*p+1][0]=t4[2]; b2[2*p+1][1]=t4[3];
        } else {
          ldsm4(t4, &Bs[st][(wn+p*16+frag_r)*PITCH + kk + frag_k]);
          b2[2*p][0]=t4[0]; b2[2*p][1]=t4[2]; b2[2*p+1][0]=t4[1]; b2[2*p+1][1]=t4[3];
        }
      }
#pragma unroll
      for(int mi=0;mi<2;mi++)
#pragma unroll
        for(int ni=0;ni<4;ni++)
          mma_f16(c[mi][ni], a4[mi], b2[ni]);
    }
    if(t+2<T){ ld(t+2); cpa_commit(); }
  }
  // epilogue
#pragma unroll
  for(int mi=0;mi<2;mi++)
#pragma unroll
  for(int ni=0;ni<4;ni++)
#pragma unroll
  for(int hh2=0;hh2<2;hh2++){
    int r = bm + wm + mi*16 + (lane>>2) + hh2*8;
    int cc = bn + wn + ni*8 + (lane&3)*2;
    float v0 = c[mi][ni][hh2*2+0], v1 = c[mi][ni][hh2*2+1];
    if(MODE==M_HOUT){
      *(uint32_t*)&Ch[cbase + (long)r*N + cc] = packh2(v0, v1);
    } else if(MODE==M_RES){
      v0 += bias[cc]   + res[(long)r*N + cc];
      v1 += bias[cc+1] + res[(long)r*N + cc + 1];
      *(float2*)&Cf[cbase + (long)r*N + cc] = make_float2(v0, v1);
    } else if(MODE==M_GELU){
      *(uint32_t*)&Ch[(long)r*N + cc] = packh2(gelu_f(v0 + bias[cc]), gelu_f(v1 + bias[cc+1]));
    } else if(MODE==M_QKV){
      int buf = cc>>10, c10 = cc&1023;
      const float* bp = (buf==0)? bias : (buf==1)? bias2 : bias3;
      int bI = r>>10, l = r&1023, hd = c10>>7, d = c10&127;
      *(uint32_t*)&Ch[(long)buf*SQKV + (((long)(bI*Hh+hd))*Lq + l)*DKc + d]
          = packh2(v0 + bp[c10], v1 + bp[c10+1]);
    } else if(MODE==M_MERGE){
      long bI = z>>3, hd = z&7;
      *(uint32_t*)&Ch[((bI*Lq + r))*Dd + hd*DKc + cc] = packh2(v0, v1);
    } else if(MODE==M_SCORE){
      const float scale = 0.08838834764831845f;
      long bI = z >> 3;
      long rowq = z*((long)Lq*Pp) + (long)r*Pp;
      long rowm = bI*((long)Lq*Lq) + (long)r*Lq;
      long rowa = z*((long)Lq*Lq) + (long)r*Lq;
      int p0 = pm[rowm + cc], p1 = pm[rowm + cc + 1];
      int m0 = msk[rowm + cc], m1 = msk[rowm + cc + 1];
      float s0v = (v0 + __half2float(qrh[rowq + p0]))*scale + res[rowa + cc];
      float s1v = (v1 + __half2float(qrh[rowq + p1]))*scale + res[rowa + cc + 1];
      if(m0==0) s0v = -60000.f;
      if(m1==0) s1v = -60000.f;
      *(uint32_t*)&Ch[cbase + (long)r*N + cc] = packh2(s0v, s1v);
    }
  }
}

// ---------------- LayerNorm -> fp16 ----------------
__global__ void ln_h(const float* __restrict__ x, const float* __restrict__ g,
                     const float* __restrict__ b, hf* __restrict__ y){
  __shared__ float red[256];
  int row = blockIdx.x;
  const float* xr = x + (size_t)row*Dd;
  float v[4]; float s = 0.f;
#pragma unroll
  for(int i=0;i<4;i++){ v[i] = xr[threadIdx.x + i*256]; s += v[i]; }
  red[threadIdx.x] = s; __syncthreads();
  for(int o=128;o>0;o>>=1){ if(threadIdx.x<o) red[threadIdx.x]+=red[threadIdx.x+o]; __syncthreads(); }
  float mean = red[0]*(1.f/Dd); __syncthreads();
  float s2 = 0.f;
#pragma unroll
  for(int i=0;i<4;i++){ float d = v[i]-mean; s2 += d*d; }
  red[threadIdx.x] = s2; __syncthreads();
  for(int o=128;o>0;o>>=1){ if(threadIdx.x<o) red[threadIdx.x]+=red[threadIdx.x+o]; __syncthreads(); }
  float inv = rsqrtf(red[0]*(1.f/Dd) + 1e-6f);
#pragma unroll
  for(int i=0;i<4;i++){
    int cidx = threadIdx.x + i*256;
    y[(long)row*Dd + cidx] = __float2half_rn(g[cidx]*(v[i]-mean)*inv + b[cidx]);
  }
}

// ---------------- weight prep: straight fp32->fp16 converts ----------------
__global__ void conv_small(const float* __restrict__ wq, const float* __restrict__ wk,
                           const float* __restrict__ wv, const float* __restrict__ wo,
                           hf* __restrict__ wc, hf* __restrict__ woh){
  int z = blockIdx.z;
  int idx = blockIdx.x*256 + threadIdx.x;    // 0..1M-1
  if(z < 3){
    const float* in = (z==0)? wq : (z==1)? wk : wv;
    int r = idx>>10, cidx = idx&1023;
    wc[(long)r*3072 + z*1024 + cidx] = __float2half_rn(in[idx]);
  } else {
    woh[idx] = __float2half_rn(wo[idx]);
  }
}
__global__ void conv_big(const float* __restrict__ w1, const float* __restrict__ w2,
                         const float* __restrict__ rk, const float* __restrict__ rv,
                         hf* __restrict__ o1, hf* __restrict__ o2,
                         hf* __restrict__ o3, hf* __restrict__ o4){
  int z = blockIdx.z;
  int idx = blockIdx.x*256 + threadIdx.x;
  const float* in = (z==0)? w1 : (z==1)? w2 : (z==2)? rk : rv;
  hf* o = (z==0)? o1 : (z==1)? o2 : (z==2)? o3 : o4;
  o[idx] = __float2half_rn(in[idx]);
}

// ---------------- fused softmax + scatter (fp16 scores in) ----------------
__global__ void softmax_scatter(const hf* __restrict__ scores, const int* __restrict__ pm,
                                hf* __restrict__ outa, hf* __restrict__ outp){
  __shared__ float red[256];
  __shared__ float sp[Pp];
  int bh = blockIdx.y;
  int b  = bh >> 3;
  int i  = blockIdx.x;
  const hf*  srow = scores + ((size_t)bh*Lq + i)*Lq;
  const int* prow = pm + ((size_t)b*Lq + i)*Lq;
#pragma unroll
  for(int k=0;k<4;k++) sp[threadIdx.x + k*256] = 0.f;
  float v[4]; float mx = -3.0e38f;
#pragma unroll
  for(int k=0;k<4;k++){
    v[k] = __half2float(srow[threadIdx.x + k*256]);
    mx = fmaxf(mx, v[k]);
  }
  red[threadIdx.x] = mx; __syncthreads();
  for(int o=128;o>0;o>>=1){ if(threadIdx.x<o) red[threadIdx.x]=fmaxf(red[threadIdx.x],red[threadIdx.x+o]); __syncthreads(); }
  mx = red[0]; __syncthreads();
  float s = 0.f;
#pragma unroll
  for(int k=0;k<4;k++){ v[k] = expf(v[k]-mx); s += v[k]; }
  red[threadIdx.x] = s; __syncthreads();
  for(int o=128;o>0;o>>=1){ if(threadIdx.x<o) red[threadIdx.x]+=red[threadIdx.x+o]; __syncthreads(); }
  float inv = 1.f/red[0];
  long obase = ((size_t)bh*Lq + i)*Lq;
#pragma unroll
  for(int k=0;k<4;k++){
    int j = threadIdx.x + k*256;
    float a = v[k]*inv;
    outa[obase + j] = __float2half_rn(a);
    atomicAdd(&sp[prow[j]], a);
  }
  __syncthreads();
  long pbase = ((size_t)bh*Lq + i)*Pp;
#pragma unroll
  for(int k=0;k<4;k++){
    int cidx = threadIdx.x + k*256;
    outp[pbase + cidx] = __float2half_rn(sp[cidx]);
  }
}

// ---------------- launch ----------------
extern "C" void kernel_launch(void* const* d_in, const int* in_sizes, int n_in,
                              void* d_out, int out_size){
  const float* content = (const float*)d_in[0];
  const int*   mask    = (const int*)  d_in[1];
  const float* r_k     = (const float*)d_in[2];
  const float* r_v     = (const float*)d_in[3];
  const int*   path_map= (const int*)  d_in[4];
  const float* ap      = (const float*)d_in[5];
  const float* wq = (const float*)d_in[6];  const float* bq = (const float*)d_in[7];
  const float* wk = (const float*)d_in[8];  const float* bk = (const float*)d_in[9];
  const float* wv = (const float*)d_in[10]; const float* bv = (const float*)d_in[11];
  const float* wo = (const float*)d_in[12]; const float* bo = (const float*)d_in[13];
  const float* ln1g = (const float*)d_in[14]; const float* ln1b = (const float*)d_in[15];
  const float* ln2g = (const float*)d_in[16]; const float* ln2b = (const float*)d_in[17];
  const float* w1 = (const float*)d_in[18]; const float* b1 = (const float*)d_in[19];
  const float* w2 = (const float*)d_in[20]; const float* b2 = (const float*)d_in[21];
  float* out = (float*)d_out;

  hf *xn,*qkv,*h,*at,*pt,*wc,*woh,*w1h,*w2h,*rk,*rv,*sc,*qr;
  float *x;
  cudaGetSymbolAddress((void**)&xn, g_xn);
  cudaGetSymbolAddress((void**)&qkv, g_qkv);
  cudaGetSymbolAddress((void**)&h, g_h);
  cudaGetSymbolAddress((void**)&at, g_attn); cudaGetSymbolAddress((void**)&pt, g_path);
  cudaGetSymbolAddress((void**)&wc, g_wc);   cudaGetSymbolAddress((void**)&woh, g_wo);
  cudaGetSymbolAddress((void**)&w1h, g_w1);  cudaGetSymbolAddress((void**)&w2h, g_w2);
  cudaGetSymbolAddress((void**)&rk, g_rk);   cudaGetSymbolAddress((void**)&rv, g_rv);
  cudaGetSymbolAddress((void**)&sc, g_scores);
  cudaGetSymbolAddress((void**)&qr, g_qr);
  cudaGetSymbolAddress((void**)&x, g_x);

  hf* q = qkv;
  hf* k = qkv + SQKV;
  hf* v = qkv + 2*SQKV;
  long sQK = (long)Lq*DKc;

  // prep (2 launches)
  conv_small<<<dim3((Dd*Dd)/256, 1, 4), 256>>>(wq, wk, wv, wo, wc, woh);
  conv_big<<<dim3((Dd*Ff)/256, 1, 4), 256>>>(w1, w2, r_k, r_v, w1h, w2h, rk, rv);

  // LN1
  ln_h<<<Bb*Lq, 256>>>(content, ln1g, ln1b, xn);

  // combined QKV GEMM (B = wc, K-major trans; N=3072)
  hgemm<M_QKV,1><<<dim3(3*Dd/128, (Bb*Lq)/64, 1),256>>>(
      xn, wc, nullptr,nullptr, bq, bk, bv, nullptr, nullptr,nullptr, nullptr,
      nullptr, qkv, 3*Dd, Dd, 0, 0,0,0,0, 0);

  // qr = q@rk^T  (B = rk, N-major; fp16 out)
  hgemm<M_HOUT,0><<<dim3(Pp/128, Lq/64, Bb*Hh),256>>>(
      q, rk, nullptr,nullptr, nullptr,nullptr,nullptr, nullptr, nullptr,nullptr, nullptr,
      nullptr, qr, Pp, DKc, 0, sQK, (long)Pp*DKc, 0,0, (long)Lq*Pp);

  // scores = (q@k^T + gather(qr))*scale + ap, masked (B = k, N-major; fp16 out)
  hgemm<M_SCORE,0><<<dim3(Lq/128, Lq/64, Bb*Hh),256>>>(
      q, k, nullptr,nullptr, nullptr, nullptr,nullptr, ap, path_map, mask, qr,
      nullptr, sc, Lq, DKc, 0, sQK, sQK, 0,0, (long)Lq*Lq);

  // fused softmax + scatter
  softmax_scatter<<<dim3(Lq, Bb*Hh),256>>>(sc, path_map, at, pt);

  // merged: out = attn@v + path@rv (both B K-major natural, trans) -> xn
  hgemm<M_MERGE,1><<<dim3(1, Lq/64, Bb*Hh),256>>>(
      at, v, pt, rv, nullptr,nullptr,nullptr, nullptr, nullptr,nullptr, nullptr,
      nullptr, xn, DKc, Lq, Pp,
      (long)Lq*Lq, sQK, (long)Lq*Pp, (long)Pp*DKc, 0);

  // x = merged@wo + bo + content  (B = wo natural, trans)
  hgemm<M_RES,1><<<dim3(Dd/128,(Bb*Lq)/64,1),256>>>(
      xn, woh, nullptr,nullptr, bo, nullptr,nullptr, content, nullptr,nullptr, nullptr,
      x, nullptr, Dd, Dd, 0, 0,0,0,0, 0);

  // LN2
  ln_h<<<Bb*Lq, 256>>>(x, ln2g, ln2b, xn);

  // h = gelu(xn@w1 + b1)  (B = w1 natural, trans)
  hgemm<M_GELU,1><<<dim3(Ff/128,(Bb*Lq)/64,1),256>>>(
      xn, w1h, nullptr,nullptr, b1, nullptr,nullptr, nullptr, nullptr,nullptr, nullptr,
      nullptr, h, Ff, Dd, 0, 0,0,0,0, 0);

  // out = h@w2 + b2 + x  (B = w2 natural, trans)
  hgemm<M_RES,1><<<dim3(Dd/128,(Bb*Lq)/64,1),256>>>(
      h, w2h, nullptr,nullptr, b2, nullptr,nullptr, x, nullptr,nullptr, nullptr,
      out, nullptr, Dd, Ff, 0, 0,0,0,0, 0);
}